// round 11
// baseline (speedup 1.0000x reference)
#include <cuda_runtime.h>
#include <cstdint>

#define NN 16384
#define HH 2048
#define H4 (HH / 4)            // 512 float4 (=ulonglong2) per row
#define KN 25
#define CHUNK 128
#define C4 (CHUNK / 4)         // 32
#define NCHUNK (HH / CHUNK)    // 16
#define RPW 4
#define NWARPS 8
#define NTHREADS 256
#define G 2
#define RPB (NWARPS * RPW * G) // 64 rows per block
#define NROWBLK (NN / RPB)     // 256
#define NQ 5
#define MAXNC 5
#define SMEM_BYTES (MAXNC * HH * 4)   // 40960

typedef unsigned long long ull;

__device__ __forceinline__ ull ffma2(ull a, ull b, ull c) {
    ull d;
    asm("fma.rn.f32x2 %0, %1, %2, %3;" : "=l"(d) : "l"(a), "l"(b), "l"(c));
    return d;
}
__device__ __forceinline__ float unpack_sum(ull v) {
    float lo, hi;
    asm("mov.b64 {%0, %1}, %2;" : "=f"(lo), "=f"(hi) : "l"(v));
    return lo + hi;
}

// NC = noise cols this slice owns; HT = also compute target dot
template <int NC, bool HT>
__device__ __forceinline__ void run_slice(
    const float* __restrict__ input, const float* __restrict__ weight,
    const float* __restrict__ bias, const int* __restrict__ target,
    const float* __restrict__ sw, const float* __restrict__ s_nb,
    float* __restrict__ out, int rb, int wid, int lane, int kbase)
{
    const ulonglong2* xg = reinterpret_cast<const ulonglong2*>(input);
    const ulonglong2* wg = reinterpret_cast<const ulonglong2*>(weight);

    #pragma unroll 1
    for (int g = 0; g < G; g++) {
        const int row0 = rb + (wid * G + g) * RPW;

        int tgt[RPW];
        if (HT) {
            #pragma unroll
            for (int r = 0; r < RPW; r++) tgt[r] = target[row0 + r];
        }

        ull acc2[RPW][NC];      // (even-h, odd-h) packed partial sums
        ull acct2[RPW];
        #pragma unroll
        for (int r = 0; r < RPW; r++) {
            acct2[r] = 0ull;
            #pragma unroll
            for (int j = 0; j < NC; j++) acc2[r][j] = 0ull;
        }

        // chunk-0 x prefetch (two natural f32x2 pairs per 16B load)
        ulonglong2 x2[RPW];
        #pragma unroll
        for (int r = 0; r < RPW; r++)
            x2[r] = xg[(size_t)(row0 + r) * H4 + lane];

        #pragma unroll 1
        for (int c = 0; c < NCHUNK; c++) {
            // prefetch next chunk's x (consumed next iteration) — load-bearing!
            const int cn = (c + 1 < NCHUNK) ? c + 1 : c;
            ulonglong2 x2n[RPW];
            #pragma unroll
            for (int r = 0; r < RPW; r++)
                x2n[r] = xg[(size_t)(row0 + r) * H4 + cn * C4 + lane];

            // target-row weights for THIS chunk: issued now, consumed after
            // the NC smem columns -> latency covered
            ulonglong2 wt2[RPW];
            if (HT) {
                #pragma unroll
                for (int r = 0; r < RPW; r++)
                    wt2[r] = wg[(size_t)tgt[r] * H4 + c * C4 + lane];
            }

            const ulonglong2* wrow = reinterpret_cast<const ulonglong2*>(sw)
                                     + c * C4 + lane;
            #pragma unroll
            for (int j = 0; j < NC; j++) {
                ulonglong2 w = wrow[j * H4];
                #pragma unroll
                for (int r = 0; r < RPW; r++) {
                    ull a = acc2[r][j];
                    a = ffma2(x2[r].x, w.x, a);
                    a = ffma2(x2[r].y, w.y, a);
                    acc2[r][j] = a;
                }
            }
            if (HT) {
                #pragma unroll
                for (int r = 0; r < RPW; r++) {
                    ull a = acct2[r];
                    a = ffma2(x2[r].x, wt2[r].x, a);
                    a = ffma2(x2[r].y, wt2[r].y, a);
                    acct2[r] = a;
                }
            }
            #pragma unroll
            for (int r = 0; r < RPW; r++) x2[r] = x2n[r];
        }

        // collapse packed halves, then warp butterfly reduction over lanes
        float acc[RPW][NC];
        float acct[RPW];
        #pragma unroll
        for (int r = 0; r < RPW; r++) {
            if (HT) acct[r] = unpack_sum(acct2[r]);
            #pragma unroll
            for (int j = 0; j < NC; j++) acc[r][j] = unpack_sum(acc2[r][j]);
        }

        #pragma unroll
        for (int off = 16; off > 0; off >>= 1) {
            #pragma unroll
            for (int r = 0; r < RPW; r++) {
                if (HT) acct[r] += __shfl_xor_sync(0xffffffffu, acct[r], off);
                #pragma unroll
                for (int j = 0; j < NC; j++)
                    acc[r][j] += __shfl_xor_sync(0xffffffffu, acc[r][j], off);
            }
        }

        // outputs
        #pragma unroll
        for (int r = 0; r < RPW; r++) {
            const int n = row0 + r;
            float* pmn_row = out + (size_t)2 * NN + (size_t)n * KN + kbase;
            #pragma unroll
            for (int j = 0; j < NC; j++) {
                if (lane == j) pmn_row[j] = expf(acc[r][j] + s_nb[j]);
            }
            if (HT && lane == NC) {
                out[n] = expf(acct[r] + bias[tgt[r]]);
            }
        }
    }
}

__global__ __launch_bounds__(NTHREADS, 3)
void nce_kernel(const float* __restrict__ input,
                const float* __restrict__ weight,
                const float* __restrict__ bias,
                const float* __restrict__ unig,
                const int* __restrict__ target,
                const int* __restrict__ noise,
                float* __restrict__ out)
{
    extern __shared__ __align__(16) float sw[];   // 5 x 2048 noise rows
    __shared__ float s_nb[MAXNC];
    __shared__ float s_nu[KN];
    __shared__ int   s_nk[MAXNC];

    const int tid   = threadIdx.x;
    const int lane  = tid & 31;
    const int wid   = tid >> 5;
    const int bid   = blockIdx.x;
    const int rbidx = bid / NQ;
    const int q     = bid - rbidx * NQ;
    const int rb    = rbidx * RPB;
    const int kbase = q * 5;
    const int nc    = 5;                 // every slice owns exactly 5 noise cols

    if (tid < nc) {
        int nk = noise[kbase + tid];
        s_nk[tid] = nk;
        s_nb[tid] = bias[nk];
    }
    if (q == 0 && tid < KN) s_nu[tid] = unig[noise[tid]];
    __syncthreads();

    // ---- early independent outputs (slice 0 only): pnn + pnt ----
    if (q == 0) {
        const size_t pnn_base = (size_t)2 * NN + (size_t)NN * KN + (size_t)rb * KN;
        #pragma unroll 1
        for (int i = tid; i < RPB * KN; i += NTHREADS)
            out[pnn_base + i] = s_nu[i % KN];
        if (tid < RPB) {
            int n = rb + tid;
            out[NN + n] = unig[target[n]];
        }
    }

    // ---- fill this slice's noise tile into smem (coalesced, once) ----
    {
        const float4* w4 = reinterpret_cast<const float4*>(weight);
        float4* s4 = reinterpret_cast<float4*>(sw);
        const int total = nc * H4;
        #pragma unroll 1
        for (int idx = tid; idx < total; idx += NTHREADS) {
            int j = idx >> 9;          // / H4
            int h = idx & (H4 - 1);
            s4[idx] = w4[(size_t)s_nk[j] * H4 + h];
        }
    }
    __syncthreads();
    // ======== free-running from here ========

    if (q == 4)
        run_slice<5, true >(input, weight, bias, target, sw, s_nb, out, rb, wid, lane, 20);
    else if (q == 0)
        run_slice<5, false>(input, weight, bias, target, sw, s_nb, out, rb, wid, lane, 0);
    else if (q == 1)
        run_slice<5, false>(input, weight, bias, target, sw, s_nb, out, rb, wid, lane, 5);
    else if (q == 2)
        run_slice<5, false>(input, weight, bias, target, sw, s_nb, out, rb, wid, lane, 10);
    else
        run_slice<5, false>(input, weight, bias, target, sw, s_nb, out, rb, wid, lane, 15);
}

extern "C" void kernel_launch(void* const* d_in, const int* in_sizes, int n_in,
                              void* d_out, int out_size) {
    const float* input  = (const float*)d_in[0];
    const float* weight = (const float*)d_in[1];
    const float* bias   = (const float*)d_in[2];
    const float* unig   = (const float*)d_in[3];
    const int*   target = (const int*)d_in[4];
    const int*   noise  = (const int*)d_in[5];
    float* out = (float*)d_out;

    cudaFuncSetAttribute(nce_kernel,
                         cudaFuncAttributeMaxDynamicSharedMemorySize, SMEM_BYTES);
    nce_kernel<<<NROWBLK * NQ, NTHREADS, SMEM_BYTES>>>(input, weight, bias, unig,
                                                       target, noise, out);
}

// round 12
// speedup vs baseline: 1.3763x; 1.3763x over previous
#include <cuda_runtime.h>
#include <cstdint>

#define NN 16384
#define HH 2048
#define H4 (HH / 4)            // 512 float4 per row
#define KN 25
#define CHUNK 128
#define C4 (CHUNK / 4)         // 32
#define NCHUNK (HH / CHUNK)    // 16
#define RPW 4
#define NWARPS 8
#define NTHREADS 256
#define RPB (NWARPS * RPW)     // 32 rows per block (G=1)
#define NROWBLK (NN / RPB)     // 512
#define NQ 4
#define MAXNC 7
#define SMEM_BYTES (MAXNC * HH * 4)   // 57344

__constant__ int c_kbase[NQ] = {0, 7, 14, 20};

// NC = noise cols this quarter owns; HT = also compute target dot
template <int NC, bool HT>
__device__ __forceinline__ void run_quarter(
    const float* __restrict__ input, const float* __restrict__ weight,
    const float* __restrict__ bias, const int* __restrict__ target,
    const float* __restrict__ sw, const float* __restrict__ s_nb,
    float* __restrict__ out, int rb, int wid, int lane, int kbase)
{
    const int row0 = rb + wid * RPW;

    int tgt[RPW];
    if (HT) {
        #pragma unroll
        for (int r = 0; r < RPW; r++) tgt[r] = target[row0 + r];
    }

    // hoisted, incremented row pointers (kills per-chunk IMAD chains)
    const float4* xp[RPW];
    const float4* wtp[RPW];
    #pragma unroll
    for (int r = 0; r < RPW; r++) {
        xp[r] = reinterpret_cast<const float4*>(input) + (size_t)(row0 + r) * H4 + lane;
        if (HT)
            wtp[r] = reinterpret_cast<const float4*>(weight) + (size_t)tgt[r] * H4 + lane;
    }

    float acc[RPW][NC];
    float acct[RPW];
    #pragma unroll
    for (int r = 0; r < RPW; r++) {
        acct[r] = 0.f;
        #pragma unroll
        for (int j = 0; j < NC; j++) acc[r][j] = 0.f;
    }

    // chunk-0 x prefetch
    float4 x4[RPW];
    #pragma unroll
    for (int r = 0; r < RPW; r++) x4[r] = xp[r][0];

    const float4* wrow = reinterpret_cast<const float4*>(sw) + lane;

    #pragma unroll 2
    for (int c = 0; c < NCHUNK; c++) {
        // prefetch next chunk's x (consumed next iteration) — load-bearing!
        const int dn = (c + 1 < NCHUNK) ? C4 : 0;
        float4 x4n[RPW];
        #pragma unroll
        for (int r = 0; r < RPW; r++) x4n[r] = xp[r][dn];

        // target-row weights for THIS chunk: issued now, consumed after
        // the NC smem columns of FFMA -> latency covered
        float4 wt4[RPW];
        if (HT) {
            #pragma unroll
            for (int r = 0; r < RPW; r++) wt4[r] = wtp[r][0];
        }

        #pragma unroll
        for (int j = 0; j < NC; j++) {
            float4 w = wrow[j * H4];
            #pragma unroll
            for (int r = 0; r < RPW; r++) {
                float a = acc[r][j];
                a = fmaf(x4[r].x, w.x, a);
                a = fmaf(x4[r].y, w.y, a);
                a = fmaf(x4[r].z, w.z, a);
                a = fmaf(x4[r].w, w.w, a);
                acc[r][j] = a;
            }
        }
        if (HT) {
            #pragma unroll
            for (int r = 0; r < RPW; r++) {
                float a = acct[r];
                a = fmaf(x4[r].x, wt4[r].x, a);
                a = fmaf(x4[r].y, wt4[r].y, a);
                a = fmaf(x4[r].z, wt4[r].z, a);
                a = fmaf(x4[r].w, wt4[r].w, a);
                acct[r] = a;
            }
        }

        #pragma unroll
        for (int r = 0; r < RPW; r++) {
            x4[r] = x4n[r];
            xp[r] += C4;
            if (HT) wtp[r] += C4;
        }
        wrow += C4;
    }

    // warp butterfly reduction over lanes (disjoint H slices)
    #pragma unroll
    for (int off = 16; off > 0; off >>= 1) {
        #pragma unroll
        for (int r = 0; r < RPW; r++) {
            if (HT) acct[r] += __shfl_xor_sync(0xffffffffu, acct[r], off);
            #pragma unroll
            for (int j = 0; j < NC; j++)
                acc[r][j] += __shfl_xor_sync(0xffffffffu, acc[r][j], off);
        }
    }

    // outputs
    #pragma unroll
    for (int r = 0; r < RPW; r++) {
        const int n = row0 + r;
        float* pmn_row = out + (size_t)2 * NN + (size_t)n * KN + kbase;
        #pragma unroll
        for (int j = 0; j < NC; j++) {
            if (lane == j) pmn_row[j] = __expf(acc[r][j] + s_nb[j]);
        }
        if (HT && lane == NC) {
            out[n] = __expf(acct[r] + bias[tgt[r]]);
        }
    }
}

__global__ __launch_bounds__(NTHREADS, 3)
void nce_kernel(const float* __restrict__ input,
                const float* __restrict__ weight,
                const float* __restrict__ bias,
                const float* __restrict__ unig,
                const int* __restrict__ target,
                const int* __restrict__ noise,
                float* __restrict__ out)
{
    extern __shared__ __align__(16) float sw[];   // up to 7 x 2048 noise rows
    __shared__ float s_nb[MAXNC];
    __shared__ float s_nu[KN];
    __shared__ int   s_nk[MAXNC];

    const int tid   = threadIdx.x;
    const int lane  = tid & 31;
    const int wid   = tid >> 5;
    const int bid   = blockIdx.x;
    const int q     = bid & (NQ - 1);
    const int rb    = (bid >> 2) * RPB;
    const int kbase = c_kbase[q];
    const int nc    = (q == 0) ? 7 : (q == 1) ? 7 : (q == 2) ? 6 : 5;

    if (tid < nc) {
        int nk = noise[kbase + tid];
        s_nk[tid] = nk;
        s_nb[tid] = bias[nk];
    }
    if (q == 0 && tid < KN) s_nu[tid] = unig[noise[tid]];
    __syncthreads();

    // ---- early independent outputs (quarter 0 only): pnn + pnt ----
    if (q == 0) {
        const size_t pnn_base = (size_t)2 * NN + (size_t)NN * KN + (size_t)rb * KN;
        #pragma unroll 1
        for (int i = tid; i < RPB * KN; i += NTHREADS)
            out[pnn_base + i] = s_nu[i % KN];
        if (tid < RPB) {
            int n = rb + tid;
            out[NN + n] = unig[target[n]];
        }
    }

    // ---- fill this quarter's noise tile into smem (coalesced, once) ----
    {
        const float4* w4 = reinterpret_cast<const float4*>(weight);
        float4* s4 = reinterpret_cast<float4*>(sw);
        const int total = nc * H4;
        #pragma unroll 1
        for (int idx = tid; idx < total; idx += NTHREADS) {
            int j = idx >> 9;          // / H4
            int h = idx & (H4 - 1);
            s4[idx] = w4[(size_t)s_nk[j] * H4 + h];
        }
    }
    __syncthreads();
    // ======== free-running from here ========

    switch (q) {
        case 0: run_quarter<7, false>(input, weight, bias, target, sw, s_nb, out, rb, wid, lane, 0);  break;
        case 1: run_quarter<7, false>(input, weight, bias, target, sw, s_nb, out, rb, wid, lane, 7);  break;
        case 2: run_quarter<6, false>(input, weight, bias, target, sw, s_nb, out, rb, wid, lane, 14); break;
        default: run_quarter<5, true>(input, weight, bias, target, sw, s_nb, out, rb, wid, lane, 20); break;
    }
}

extern "C" void kernel_launch(void* const* d_in, const int* in_sizes, int n_in,
                              void* d_out, int out_size) {
    const float* input  = (const float*)d_in[0];
    const float* weight = (const float*)d_in[1];
    const float* bias   = (const float*)d_in[2];
    const float* unig   = (const float*)d_in[3];
    const int*   target = (const int*)d_in[4];
    const int*   noise  = (const int*)d_in[5];
    float* out = (float*)d_out;

    cudaFuncSetAttribute(nce_kernel,
                         cudaFuncAttributeMaxDynamicSharedMemorySize, SMEM_BYTES);
    nce_kernel<<<NROWBLK * NQ, NTHREADS, SMEM_BYTES>>>(input, weight, bias, unig,
                                                       target, noise, out);
}